// round 1
// baseline (speedup 1.0000x reference)
#include <cuda_runtime.h>
#include <cuda_bf16.h>

// Problem constants (fixed shapes)
#define N_MAX 50000
#define M_MAX 800000
#define D 96          // K*FAC
#define KCAP 8
#define FAC 12

// Static scratch (no allocations allowed)
__device__ float g_z[N_MAX * D];        // normalized per-capsule features (read-only per layer)
__device__ float g_c[N_MAX * D];        // cluster centers, updated in place
__device__ float g_wt[D * 256];         // W transposed to [out=96][in=256]
__device__ int   g_deg[N_MAX];
__device__ int   g_rowptr[N_MAX + 1];
__device__ int   g_cursor[N_MAX];
__device__ int   g_colsrc[M_MAX];

// ---------------------------------------------------------------------------
// W_init [K,256,FAC] -> g_wt [96][256]
__global__ void wt_kernel(const float* __restrict__ W) {
    int tid = blockIdx.x * blockDim.x + threadIdx.x;
    if (tid < D * 256) {
        int o = tid >> 8, i = tid & 255;
        int k = o / FAC, oo = o % FAC;
        g_wt[tid] = W[k * (256 * FAC) + i * FAC + oo];
    }
}

// ---------------------------------------------------------------------------
// Init layer: g_c[n][o] = relu( X[n,:] . Wt[o,:] + b[o] )
// block = 96 threads (one output each), 32 nodes per block via smem X tile.
__global__ void __launch_bounds__(96) init_gemm(const float* __restrict__ X,
                                                const float* __restrict__ bv, int n) {
    __shared__ float xs[32][256];
    int t = threadIdx.x;
    int nb = blockIdx.x * 32;
    for (int j = t; j < 32 * 256; j += 96) {
        int q = j >> 8;
        xs[q][j & 255] = (nb + q < n) ? X[nb * 256 + j] : 0.f;
    }
    __syncthreads();

    float acc[32];
#pragma unroll
    for (int q = 0; q < 32; q++) acc[q] = 0.f;

    const float4* wrow = (const float4*)(g_wt + t * 256);
#pragma unroll 2
    for (int i4 = 0; i4 < 64; i4++) {
        float4 w = wrow[i4];
#pragma unroll
        for (int q = 0; q < 32; q++) {
            float4 xv = *(const float4*)&xs[q][i4 * 4];
            acc[q] += w.x * xv.x + w.y * xv.y + w.z * xv.z + w.w * xv.w;
        }
    }
    float bb = bv[t];
    int cnt = min(32, n - nb);
    for (int q = 0; q < cnt; q++)
        g_c[(nb + q) * D + t] = fmaxf(acc[q] + bb, 0.f);
}

// ---------------------------------------------------------------------------
// CSR build (per replay): zero -> hist -> scan -> scatter -> per-row sort
__global__ void zero_kernel(int n) {
    int i = blockIdx.x * blockDim.x + threadIdx.x;
    if (i < n) g_deg[i] = 0;
}

__global__ void hist_kernel(const int* __restrict__ edges, int m) {
    int e = blockIdx.x * blockDim.x + threadIdx.x;
    if (e < m) atomicAdd(&g_deg[edges[m + e]], 1);
}

__global__ void scan_kernel(int n) {
    __shared__ int wsum[32];
    int t = threadIdx.x, lane = t & 31, wid = t >> 5;
    int running = 0;
    for (int base = 0; base < n; base += 1024) {
        int idx = base + t;
        int v = (idx < n) ? g_deg[idx] : 0;
        int x = v;
#pragma unroll
        for (int off = 1; off < 32; off <<= 1) {
            int y = __shfl_up_sync(0xffffffffu, x, off);
            if (lane >= off) x += y;
        }
        if (lane == 31) wsum[wid] = x;
        __syncthreads();
        if (wid == 0) {
            int w = wsum[lane];
#pragma unroll
            for (int off = 1; off < 32; off <<= 1) {
                int y = __shfl_up_sync(0xffffffffu, w, off);
                if (lane >= off) w += y;
            }
            wsum[lane] = w;
        }
        __syncthreads();
        int pre = (wid > 0) ? wsum[wid - 1] : 0;
        int excl = running + pre + x - v;
        if (idx < n) { g_rowptr[idx] = excl; g_cursor[idx] = excl; }
        int total = wsum[31];
        __syncthreads();
        running += total;
    }
    if (t == 0) g_rowptr[n] = running;
}

__global__ void scatter_kernel(const int* __restrict__ edges, int m) {
    int e = blockIdx.x * blockDim.x + threadIdx.x;
    if (e < m) {
        int d = edges[m + e];
        int pos = atomicAdd(&g_cursor[d], 1);
        g_colsrc[pos] = edges[e];
    }
}

// Sort each row's src list so fp accumulation order is deterministic.
__global__ void sort_rows(int n) {
    int node = blockIdx.x * blockDim.x + threadIdx.x;
    if (node >= n) return;
    int s = g_rowptr[node], e = g_rowptr[node + 1];
    for (int i = s + 1; i < e; i++) {
        int v = g_colsrc[i];
        int j = i - 1;
        while (j >= s && g_colsrc[j] > v) { g_colsrc[j + 1] = g_colsrc[j]; j--; }
        g_colsrc[j + 1] = v;
    }
}

// ---------------------------------------------------------------------------
// Prep per layer: z = l2norm(relu(c)) per capsule; c = z.
// one thread per (node, capsule).
__global__ void prep_kernel(int n) {
    int idx = blockIdx.x * blockDim.x + threadIdx.x;
    if (idx >= n * KCAP) return;
    float4* cp = (float4*)(g_c + idx * FAC);
    float4 x0 = cp[0], x1 = cp[1], x2 = cp[2];
    x0.x = fmaxf(x0.x, 0.f); x0.y = fmaxf(x0.y, 0.f); x0.z = fmaxf(x0.z, 0.f); x0.w = fmaxf(x0.w, 0.f);
    x1.x = fmaxf(x1.x, 0.f); x1.y = fmaxf(x1.y, 0.f); x1.z = fmaxf(x1.z, 0.f); x1.w = fmaxf(x1.w, 0.f);
    x2.x = fmaxf(x2.x, 0.f); x2.y = fmaxf(x2.y, 0.f); x2.z = fmaxf(x2.z, 0.f); x2.w = fmaxf(x2.w, 0.f);
    float s = x0.x*x0.x + x0.y*x0.y + x0.z*x0.z + x0.w*x0.w
            + x1.x*x1.x + x1.y*x1.y + x1.z*x1.z + x1.w*x1.w
            + x2.x*x2.x + x2.y*x2.y + x2.z*x2.z + x2.w*x2.w;
    float rn = rsqrtf(s + 1e-12f);
    x0.x *= rn; x0.y *= rn; x0.z *= rn; x0.w *= rn;
    x1.x *= rn; x1.y *= rn; x1.z *= rn; x1.w *= rn;
    x2.x *= rn; x2.y *= rn; x2.z *= rn; x2.w *= rn;
    float4* zp = (float4*)(g_z + idx * FAC);
    zp[0] = x0; zp[1] = x1; zp[2] = x2;
    cp[0] = x0; cp[1] = x1; cp[2] = x2;
}

// ---------------------------------------------------------------------------
// One routing iteration. 8-lane group per dst node (lane = capsule),
// 4 nodes per warp, 32 nodes per 256-thread block. c updated in place
// (each node owned by exactly one group).
__global__ void __launch_bounds__(256) routing_kernel(int n) {
    int lane = threadIdx.x & 31;
    int warp = threadIdx.x >> 5;
    int group = lane >> 3;
    int cap = lane & 7;
    unsigned mask = 0xFFu << (group << 3);
    int node = (blockIdx.x * 8 + warp) * 4 + group;
    if (node >= n) return;

    int off = node * D + cap * FAC;
    const float4* cb = (const float4*)(g_c + off);
    float4 c0 = cb[0], c1 = cb[1], c2 = cb[2];

    float4 acc0 = make_float4(0.f, 0.f, 0.f, 0.f);
    float4 acc1 = make_float4(0.f, 0.f, 0.f, 0.f);
    float4 acc2 = make_float4(0.f, 0.f, 0.f, 0.f);

    int e = g_rowptr[node];
    int eend = g_rowptr[node + 1];

    float4 A0 = make_float4(0.f,0.f,0.f,0.f), A1 = A0, A2 = A0;
    if (e < eend) {
        const float4* zp = (const float4*)(g_z + g_colsrc[e] * D + cap * FAC);
        A0 = zp[0]; A1 = zp[1]; A2 = zp[2];
    }
    while (e < eend) {
        float4 B0 = A0, B1 = A1, B2 = A2;
        if (e + 1 < eend) {  // prefetch next src row
            const float4* zp = (const float4*)(g_z + g_colsrc[e + 1] * D + cap * FAC);
            B0 = zp[0]; B1 = zp[1]; B2 = zp[2];
        }
        float att = A0.x*c0.x + A0.y*c0.y + A0.z*c0.z + A0.w*c0.w
                  + A1.x*c1.x + A1.y*c1.y + A1.z*c1.z + A1.w*c1.w
                  + A2.x*c2.x + A2.y*c2.y + A2.z*c2.z + A2.w*c2.w;
        float mx = att;
        mx = fmaxf(mx, __shfl_xor_sync(mask, mx, 1));
        mx = fmaxf(mx, __shfl_xor_sync(mask, mx, 2));
        mx = fmaxf(mx, __shfl_xor_sync(mask, mx, 4));
        float ex = __expf(att - mx);
        float sm = ex;
        sm += __shfl_xor_sync(mask, sm, 1);
        sm += __shfl_xor_sync(mask, sm, 2);
        sm += __shfl_xor_sync(mask, sm, 4);
        float p = __fdividef(ex, sm);
        acc0.x += p * A0.x; acc0.y += p * A0.y; acc0.z += p * A0.z; acc0.w += p * A0.w;
        acc1.x += p * A1.x; acc1.y += p * A1.y; acc1.z += p * A1.z; acc1.w += p * A1.w;
        acc2.x += p * A2.x; acc2.y += p * A2.y; acc2.z += p * A2.z; acc2.w += p * A2.w;
        A0 = B0; A1 = B1; A2 = B2;
        e++;
    }

    const float4* zb = (const float4*)(g_z + off);
    float4 z0 = zb[0], z1 = zb[1], z2 = zb[2];
    float4 v0 = make_float4(z0.x + acc0.x, z0.y + acc0.y, z0.z + acc0.z, z0.w + acc0.w);
    float4 v1 = make_float4(z1.x + acc1.x, z1.y + acc1.y, z1.z + acc1.z, z1.w + acc1.w);
    float4 v2 = make_float4(z2.x + acc2.x, z2.y + acc2.y, z2.z + acc2.z, z2.w + acc2.w);
    float s = v0.x*v0.x + v0.y*v0.y + v0.z*v0.z + v0.w*v0.w
            + v1.x*v1.x + v1.y*v1.y + v1.z*v1.z + v1.w*v1.w
            + v2.x*v2.x + v2.y*v2.y + v2.z*v2.z + v2.w*v2.w;
    float rn = rsqrtf(s + 1e-12f);
    v0.x *= rn; v0.y *= rn; v0.z *= rn; v0.w *= rn;
    v1.x *= rn; v1.y *= rn; v1.z *= rn; v1.w *= rn;
    v2.x *= rn; v2.y *= rn; v2.z *= rn; v2.w *= rn;
    float4* co = (float4*)(g_c + off);
    co[0] = v0; co[1] = v1; co[2] = v2;
}

// ---------------------------------------------------------------------------
__global__ void relu_out(float* __restrict__ out, int tot) {
    int i = blockIdx.x * blockDim.x + threadIdx.x;
    if (i < tot) out[i] = fmaxf(g_c[i], 0.f);
}

// ---------------------------------------------------------------------------
extern "C" void kernel_launch(void* const* d_in, const int* in_sizes, int n_in,
                              void* d_out, int out_size) {
    const float* X     = (const float*)d_in[0];
    const int*   edges = (const int*)d_in[1];
    const float* W     = (const float*)d_in[2];
    const float* b     = (const float*)d_in[3];
    int n = in_sizes[0] / 256;   // 50000
    int m = in_sizes[1] / 2;     // 800000

    // weights transpose + init layer
    wt_kernel<<<(D * 256 + 255) / 256, 256>>>(W);
    init_gemm<<<(n + 31) / 32, 96>>>(X, b, n);

    // CSR by dst (deterministic: rows sorted by src)
    zero_kernel<<<(n + 255) / 256, 256>>>(n);
    hist_kernel<<<(m + 255) / 256, 256>>>(edges, m);
    scan_kernel<<<1, 1024>>>(n);
    scatter_kernel<<<(m + 255) / 256, 256>>>(edges, m);
    sort_rows<<<(n + 255) / 256, 256>>>(n);

    // 4 layers x (prep + 6 routing iterations)
    for (int layer = 0; layer < 4; layer++) {
        prep_kernel<<<(n * KCAP + 255) / 256, 256>>>(n);
        for (int it = 0; it < 6; it++)
            routing_kernel<<<(n + 31) / 32, 256>>>(n);
    }

    relu_out<<<(n * D + 255) / 256, 256>>>((float*)d_out, n * D);
}

// round 2
// speedup vs baseline: 1.0280x; 1.0280x over previous
#include <cuda_runtime.h>
#include <cuda_fp16.h>

// Problem constants (fixed shapes)
#define N_MAX 50000
#define M_MAX 800000
#define D 96          // K*FAC
#define KCAP 8
#define FAC 12

// Static scratch (no allocations allowed)
__device__ __half g_zh[N_MAX * D];      // fp16 normalized features (gather source)
__device__ float  g_z32[N_MAX * D];     // fp32 normalized features (dst self-term)
__device__ float  g_c[N_MAX * D];       // cluster centers, fp32, updated in place
__device__ float  g_wt[D * 256];        // W transposed to [out=96][in=256]
__device__ int    g_deg[N_MAX];
__device__ int    g_rowptr[N_MAX + 1];
__device__ int    g_cursor[N_MAX];
__device__ int    g_colsrc[M_MAX];

// ---------------------------------------------------------------------------
// W_init [K,256,FAC] -> g_wt [96][256]
__global__ void wt_kernel(const float* __restrict__ W) {
    int tid = blockIdx.x * blockDim.x + threadIdx.x;
    if (tid < D * 256) {
        int o = tid >> 8, i = tid & 255;
        int k = o / FAC, oo = o % FAC;
        g_wt[tid] = W[k * (256 * FAC) + i * FAC + oo];
    }
}

// ---------------------------------------------------------------------------
// Init layer: g_c[n][o] = relu( X[n,:] . Wt[o,:] + b[o] )
__global__ void __launch_bounds__(96) init_gemm(const float* __restrict__ X,
                                                const float* __restrict__ bv, int n) {
    __shared__ float xs[32][256];
    int t = threadIdx.x;
    int nb = blockIdx.x * 32;
    for (int j = t; j < 32 * 256; j += 96) {
        int q = j >> 8;
        xs[q][j & 255] = (nb + q < n) ? X[nb * 256 + j] : 0.f;
    }
    __syncthreads();

    float acc[32];
#pragma unroll
    for (int q = 0; q < 32; q++) acc[q] = 0.f;

    const float4* wrow = (const float4*)(g_wt + t * 256);
#pragma unroll 2
    for (int i4 = 0; i4 < 64; i4++) {
        float4 w = wrow[i4];
#pragma unroll
        for (int q = 0; q < 32; q++) {
            float4 xv = *(const float4*)&xs[q][i4 * 4];
            acc[q] += w.x * xv.x + w.y * xv.y + w.z * xv.z + w.w * xv.w;
        }
    }
    float bb = bv[t];
    int cnt = min(32, n - nb);
    for (int q = 0; q < cnt; q++)
        g_c[(nb + q) * D + t] = fmaxf(acc[q] + bb, 0.f);
}

// ---------------------------------------------------------------------------
// CSR build (per replay): zero -> hist -> scan -> scatter -> per-row sort
__global__ void zero_kernel(int n) {
    int i = blockIdx.x * blockDim.x + threadIdx.x;
    if (i < n) g_deg[i] = 0;
}

__global__ void hist_kernel(const int* __restrict__ edges, int m) {
    int e = blockIdx.x * blockDim.x + threadIdx.x;
    if (e < m) atomicAdd(&g_deg[edges[m + e]], 1);
}

__global__ void scan_kernel(int n) {
    __shared__ int wsum[32];
    int t = threadIdx.x, lane = t & 31, wid = t >> 5;
    int running = 0;
    for (int base = 0; base < n; base += 1024) {
        int idx = base + t;
        int v = (idx < n) ? g_deg[idx] : 0;
        int x = v;
#pragma unroll
        for (int off = 1; off < 32; off <<= 1) {
            int y = __shfl_up_sync(0xffffffffu, x, off);
            if (lane >= off) x += y;
        }
        if (lane == 31) wsum[wid] = x;
        __syncthreads();
        if (wid == 0) {
            int w = wsum[lane];
#pragma unroll
            for (int off = 1; off < 32; off <<= 1) {
                int y = __shfl_up_sync(0xffffffffu, w, off);
                if (lane >= off) w += y;
            }
            wsum[lane] = w;
        }
        __syncthreads();
        int pre = (wid > 0) ? wsum[wid - 1] : 0;
        int excl = running + pre + x - v;
        if (idx < n) { g_rowptr[idx] = excl; g_cursor[idx] = excl; }
        int total = wsum[31];
        __syncthreads();
        running += total;
    }
    if (t == 0) g_rowptr[n] = running;
}

__global__ void scatter_kernel(const int* __restrict__ edges, int m) {
    int e = blockIdx.x * blockDim.x + threadIdx.x;
    if (e < m) {
        int d = edges[m + e];
        int pos = atomicAdd(&g_cursor[d], 1);
        g_colsrc[pos] = edges[e];
    }
}

// Sort each row's src list so fp accumulation order is deterministic.
__global__ void sort_rows(int n) {
    int node = blockIdx.x * blockDim.x + threadIdx.x;
    if (node >= n) return;
    int s = g_rowptr[node], e = g_rowptr[node + 1];
    for (int i = s + 1; i < e; i++) {
        int v = g_colsrc[i];
        int j = i - 1;
        while (j >= s && g_colsrc[j] > v) { g_colsrc[j + 1] = g_colsrc[j]; j--; }
        g_colsrc[j + 1] = v;
    }
}

// ---------------------------------------------------------------------------
// Prep per layer: z = l2norm(relu(c)); store fp32 (self-term + c) and fp16 (gather).
__global__ void prep_kernel(int n) {
    int idx = blockIdx.x * blockDim.x + threadIdx.x;
    if (idx >= n * KCAP) return;
    float4* cp = (float4*)(g_c + idx * FAC);
    float4 x0 = cp[0], x1 = cp[1], x2 = cp[2];
    x0.x = fmaxf(x0.x, 0.f); x0.y = fmaxf(x0.y, 0.f); x0.z = fmaxf(x0.z, 0.f); x0.w = fmaxf(x0.w, 0.f);
    x1.x = fmaxf(x1.x, 0.f); x1.y = fmaxf(x1.y, 0.f); x1.z = fmaxf(x1.z, 0.f); x1.w = fmaxf(x1.w, 0.f);
    x2.x = fmaxf(x2.x, 0.f); x2.y = fmaxf(x2.y, 0.f); x2.z = fmaxf(x2.z, 0.f); x2.w = fmaxf(x2.w, 0.f);
    float s = x0.x*x0.x + x0.y*x0.y + x0.z*x0.z + x0.w*x0.w
            + x1.x*x1.x + x1.y*x1.y + x1.z*x1.z + x1.w*x1.w
            + x2.x*x2.x + x2.y*x2.y + x2.z*x2.z + x2.w*x2.w;
    float rn = rsqrtf(s + 1e-12f);
    x0.x *= rn; x0.y *= rn; x0.z *= rn; x0.w *= rn;
    x1.x *= rn; x1.y *= rn; x1.z *= rn; x1.w *= rn;
    x2.x *= rn; x2.y *= rn; x2.z *= rn; x2.w *= rn;
    float4* zp = (float4*)(g_z32 + idx * FAC);
    zp[0] = x0; zp[1] = x1; zp[2] = x2;
    cp[0] = x0; cp[1] = x1; cp[2] = x2;
    // fp16 copy for gathers: 12 halves = 3 x uint2 (8B aligned)
    uint2* zh = (uint2*)(g_zh + idx * FAC);
    __half2 h0 = __floats2half2_rn(x0.x, x0.y);
    __half2 h1 = __floats2half2_rn(x0.z, x0.w);
    __half2 h2 = __floats2half2_rn(x1.x, x1.y);
    __half2 h3 = __floats2half2_rn(x1.z, x1.w);
    __half2 h4 = __floats2half2_rn(x2.x, x2.y);
    __half2 h5 = __floats2half2_rn(x2.z, x2.w);
    zh[0] = make_uint2(*(unsigned*)&h0, *(unsigned*)&h1);
    zh[1] = make_uint2(*(unsigned*)&h2, *(unsigned*)&h3);
    zh[2] = make_uint2(*(unsigned*)&h4, *(unsigned*)&h5);
}

// ---------------------------------------------------------------------------
// One routing iteration. 8-lane group per dst node (lane = capsule),
// 4 nodes per warp. c updated in place; gathers read fp16 z.
__global__ void __launch_bounds__(256) routing_kernel(int n) {
    int lane = threadIdx.x & 31;
    int warp = threadIdx.x >> 5;
    int group = lane >> 3;
    int cap = lane & 7;
    unsigned mask = 0xFFu << (group << 3);
    int node = (blockIdx.x * 8 + warp) * 4 + group;
    if (node >= n) return;

    int off = node * D + cap * FAC;
    const float4* cb = (const float4*)(g_c + off);
    float4 c0 = cb[0], c1 = cb[1], c2 = cb[2];

    float acc[12];
#pragma unroll
    for (int i = 0; i < 12; i++) acc[i] = 0.f;

    int e = g_rowptr[node];
    int eend = g_rowptr[node + 1];

    uint2 A0 = make_uint2(0, 0), A1 = A0, A2 = A0;
    if (e < eend) {
        const uint2* zp = (const uint2*)(g_zh + g_colsrc[e] * D + cap * FAC);
        A0 = zp[0]; A1 = zp[1]; A2 = zp[2];
    }
    while (e < eend) {
        uint2 B0 = A0, B1 = A1, B2 = A2;
        if (e + 1 < eend) {  // prefetch next src row
            const uint2* zp = (const uint2*)(g_zh + g_colsrc[e + 1] * D + cap * FAC);
            B0 = zp[0]; B1 = zp[1]; B2 = zp[2];
        }
        // convert 12 halves -> fp32
        float f[12];
        {
            float2 t;
            t = __half22float2(*(__half2*)&A0.x); f[0] = t.x; f[1] = t.y;
            t = __half22float2(*(__half2*)&A0.y); f[2] = t.x; f[3] = t.y;
            t = __half22float2(*(__half2*)&A1.x); f[4] = t.x; f[5] = t.y;
            t = __half22float2(*(__half2*)&A1.y); f[6] = t.x; f[7] = t.y;
            t = __half22float2(*(__half2*)&A2.x); f[8] = t.x; f[9] = t.y;
            t = __half22float2(*(__half2*)&A2.y); f[10] = t.x; f[11] = t.y;
        }
        float att = f[0]*c0.x + f[1]*c0.y + f[2]*c0.z + f[3]*c0.w
                  + f[4]*c1.x + f[5]*c1.y + f[6]*c1.z + f[7]*c1.w
                  + f[8]*c2.x + f[9]*c2.y + f[10]*c2.z + f[11]*c2.w;
        // z,c are unit vectors per capsule -> att in [-1,1]; exp is safe, no max-sub.
        float ex = __expf(att);
        float sm = ex;
        sm += __shfl_xor_sync(mask, sm, 1);
        sm += __shfl_xor_sync(mask, sm, 2);
        sm += __shfl_xor_sync(mask, sm, 4);
        float p = __fdividef(ex, sm);
#pragma unroll
        for (int i = 0; i < 12; i++) acc[i] += p * f[i];
        A0 = B0; A1 = B1; A2 = B2;
        e++;
    }

    const float4* zb = (const float4*)(g_z32 + off);
    float4 z0 = zb[0], z1 = zb[1], z2 = zb[2];
    float v[12];
    v[0] = z0.x + acc[0];  v[1] = z0.y + acc[1];  v[2]  = z0.z + acc[2];  v[3]  = z0.w + acc[3];
    v[4] = z1.x + acc[4];  v[5] = z1.y + acc[5];  v[6]  = z1.z + acc[6];  v[7]  = z1.w + acc[7];
    v[8] = z2.x + acc[8];  v[9] = z2.y + acc[9];  v[10] = z2.z + acc[10]; v[11] = z2.w + acc[11];
    float s = 0.f;
#pragma unroll
    for (int i = 0; i < 12; i++) s += v[i] * v[i];
    float rn = rsqrtf(s + 1e-12f);
    float4* co = (float4*)(g_c + off);
    co[0] = make_float4(v[0]*rn, v[1]*rn, v[2]*rn, v[3]*rn);
    co[1] = make_float4(v[4]*rn, v[5]*rn, v[6]*rn, v[7]*rn);
    co[2] = make_float4(v[8]*rn, v[9]*rn, v[10]*rn, v[11]*rn);
}

// ---------------------------------------------------------------------------
__global__ void relu_out(float* __restrict__ out, int tot) {
    int i = blockIdx.x * blockDim.x + threadIdx.x;
    if (i < tot) out[i] = fmaxf(g_c[i], 0.f);
}

// ---------------------------------------------------------------------------
extern "C" void kernel_launch(void* const* d_in, const int* in_sizes, int n_in,
                              void* d_out, int out_size) {
    const float* X     = (const float*)d_in[0];
    const int*   edges = (const int*)d_in[1];
    const float* W     = (const float*)d_in[2];
    const float* b     = (const float*)d_in[3];
    int n = in_sizes[0] / 256;   // 50000
    int m = in_sizes[1] / 2;     // 800000

    // weights transpose + init layer
    wt_kernel<<<(D * 256 + 255) / 256, 256>>>(W);
    init_gemm<<<(n + 31) / 32, 96>>>(X, b, n);

    // CSR by dst (deterministic: rows sorted by src)
    zero_kernel<<<(n + 255) / 256, 256>>>(n);
    hist_kernel<<<(m + 255) / 256, 256>>>(edges, m);
    scan_kernel<<<1, 1024>>>(n);
    scatter_kernel<<<(m + 255) / 256, 256>>>(edges, m);
    sort_rows<<<(n + 255) / 256, 256>>>(n);

    // 4 layers x (prep + 6 routing iterations)
    for (int layer = 0; layer < 4; layer++) {
        prep_kernel<<<(n * KCAP + 255) / 256, 256>>>(n);
        for (int it = 0; it < 6; it++)
            routing_kernel<<<(n + 31) / 32, 256>>>(n);
    }

    relu_out<<<(n * D + 255) / 256, 256>>>((float*)d_out, n * D);
}

// round 3
// speedup vs baseline: 1.2916x; 1.2565x over previous
#include <cuda_runtime.h>
#include <cuda_fp16.h>

// Problem constants (fixed shapes)
#define N_MAX 50000
#define M_MAX 800000
#define D 96          // K*FAC
#define KCAP 8
#define FAC 12

#define CAP 24                  // cached neighbors per node in smem
#define NSTRIDE 4640            // bytes per node slab: CAP*192 + 32 pad
#define ROUTE_SMEM (16 * NSTRIDE)  // 74240 B per 128-thread block (16 nodes)

// Static scratch (no allocations allowed)
__device__ __half g_zh[N_MAX * D];      // fp16 normalized features (gather source)
__device__ float  g_c[N_MAX * D];       // node state, fp32
__device__ float  g_wt[D * 256];        // W transposed to [out=96][in=256]
__device__ int    g_deg[N_MAX];
__device__ int    g_rowptr[N_MAX + 1];
__device__ int    g_cursor[N_MAX];
__device__ int    g_colsrc[M_MAX];
__device__ int    g_dhist[64];
__device__ int    g_dcur[64];
__device__ int    g_perm[N_MAX];

// ---------------------------------------------------------------------------
__global__ void wt_kernel(const float* __restrict__ W) {
    int tid = blockIdx.x * blockDim.x + threadIdx.x;
    if (tid < D * 256) {
        int o = tid >> 8, i = tid & 255;
        int k = o / FAC, oo = o % FAC;
        g_wt[tid] = W[k * (256 * FAC) + i * FAC + oo];
    }
}

// ---------------------------------------------------------------------------
// Init layer: g_c[n][o] = relu( X[n,:] . Wt[o,:] + b[o] )
__global__ void __launch_bounds__(96) init_gemm(const float* __restrict__ X,
                                                const float* __restrict__ bv, int n) {
    __shared__ float xs[32][256];
    int t = threadIdx.x;
    int nb = blockIdx.x * 32;
    for (int j = t; j < 32 * 256; j += 96) {
        int q = j >> 8;
        xs[q][j & 255] = (nb + q < n) ? X[nb * 256 + j] : 0.f;
    }
    __syncthreads();

    float acc[32];
#pragma unroll
    for (int q = 0; q < 32; q++) acc[q] = 0.f;

    const float4* wrow = (const float4*)(g_wt + t * 256);
#pragma unroll 2
    for (int i4 = 0; i4 < 64; i4++) {
        float4 w = wrow[i4];
#pragma unroll
        for (int q = 0; q < 32; q++) {
            float4 xv = *(const float4*)&xs[q][i4 * 4];
            acc[q] += w.x * xv.x + w.y * xv.y + w.z * xv.z + w.w * xv.w;
        }
    }
    float bb = bv[t];
    int cnt = min(32, n - nb);
    for (int q = 0; q < cnt; q++)
        g_c[(nb + q) * D + t] = fmaxf(acc[q] + bb, 0.f);
}

// ---------------------------------------------------------------------------
// CSR build: zero -> hist -> scan -> scatter -> per-row sort
__global__ void zero_kernel(int n) {
    int i = blockIdx.x * blockDim.x + threadIdx.x;
    if (i < n) g_deg[i] = 0;
    if (i < 64) { g_dhist[i] = 0; }
}

__global__ void hist_kernel(const int* __restrict__ edges, int m) {
    int e = blockIdx.x * blockDim.x + threadIdx.x;
    if (e < m) atomicAdd(&g_deg[edges[m + e]], 1);
}

__global__ void scan_kernel(int n) {
    __shared__ int wsum[32];
    int t = threadIdx.x, lane = t & 31, wid = t >> 5;
    int running = 0;
    for (int base = 0; base < n; base += 1024) {
        int idx = base + t;
        int v = (idx < n) ? g_deg[idx] : 0;
        int x = v;
#pragma unroll
        for (int off = 1; off < 32; off <<= 1) {
            int y = __shfl_up_sync(0xffffffffu, x, off);
            if (lane >= off) x += y;
        }
        if (lane == 31) wsum[wid] = x;
        __syncthreads();
        if (wid == 0) {
            int w = wsum[lane];
#pragma unroll
            for (int off = 1; off < 32; off <<= 1) {
                int y = __shfl_up_sync(0xffffffffu, w, off);
                if (lane >= off) w += y;
            }
            wsum[lane] = w;
        }
        __syncthreads();
        int pre = (wid > 0) ? wsum[wid - 1] : 0;
        int excl = running + pre + x - v;
        if (idx < n) { g_rowptr[idx] = excl; g_cursor[idx] = excl; }
        int total = wsum[31];
        __syncthreads();
        running += total;
    }
    if (t == 0) g_rowptr[n] = running;
}

__global__ void scatter_kernel(const int* __restrict__ edges, int m) {
    int e = blockIdx.x * blockDim.x + threadIdx.x;
    if (e < m) {
        int d = edges[m + e];
        int pos = atomicAdd(&g_cursor[d], 1);
        g_colsrc[pos] = edges[e];
    }
}

// Sort each row's src list: deterministic accumulation order.
__global__ void sort_rows(int n) {
    int node = blockIdx.x * blockDim.x + threadIdx.x;
    if (node >= n) return;
    int s = g_rowptr[node], e = g_rowptr[node + 1];
    for (int i = s + 1; i < e; i++) {
        int v = g_colsrc[i];
        int j = i - 1;
        while (j >= s && g_colsrc[j] > v) { g_colsrc[j + 1] = g_colsrc[j]; j--; }
        g_colsrc[j + 1] = v;
    }
}

// ---------------------------------------------------------------------------
// Degree-balanced permutation: bucket nodes by (clamped) degree.
__global__ void dhist_kernel(int n) {
    int i = blockIdx.x * blockDim.x + threadIdx.x;
    if (i < n) {
        int d = min(g_rowptr[i + 1] - g_rowptr[i], 63);
        atomicAdd(&g_dhist[d], 1);
    }
}

__global__ void dscan_kernel() {
    if (threadIdx.x == 0) {
        int run = 0;
        for (int i = 0; i < 64; i++) { g_dcur[i] = run; run += g_dhist[i]; }
    }
}

__global__ void dscatter_kernel(int n) {
    int i = blockIdx.x * blockDim.x + threadIdx.x;
    if (i < n) {
        int d = min(g_rowptr[i + 1] - g_rowptr[i], 63);
        int pos = atomicAdd(&g_dcur[d], 1);
        g_perm[pos] = i;
    }
}

// ---------------------------------------------------------------------------
// Prep per layer: zh = fp16( l2norm(relu(c)) ). g_c untouched.
__global__ void prep_kernel(int n) {
    int idx = blockIdx.x * blockDim.x + threadIdx.x;
    if (idx >= n * KCAP) return;
    const float4* cp = (const float4*)(g_c + idx * FAC);
    float4 x0 = cp[0], x1 = cp[1], x2 = cp[2];
    x0.x = fmaxf(x0.x, 0.f); x0.y = fmaxf(x0.y, 0.f); x0.z = fmaxf(x0.z, 0.f); x0.w = fmaxf(x0.w, 0.f);
    x1.x = fmaxf(x1.x, 0.f); x1.y = fmaxf(x1.y, 0.f); x1.z = fmaxf(x1.z, 0.f); x1.w = fmaxf(x1.w, 0.f);
    x2.x = fmaxf(x2.x, 0.f); x2.y = fmaxf(x2.y, 0.f); x2.z = fmaxf(x2.z, 0.f); x2.w = fmaxf(x2.w, 0.f);
    float s = x0.x*x0.x + x0.y*x0.y + x0.z*x0.z + x0.w*x0.w
            + x1.x*x1.x + x1.y*x1.y + x1.z*x1.z + x1.w*x1.w
            + x2.x*x2.x + x2.y*x2.y + x2.z*x2.z + x2.w*x2.w;
    float rn = rsqrtf(s + 1e-12f);
    __half2 h0 = __floats2half2_rn(x0.x*rn, x0.y*rn);
    __half2 h1 = __floats2half2_rn(x0.z*rn, x0.w*rn);
    __half2 h2 = __floats2half2_rn(x1.x*rn, x1.y*rn);
    __half2 h3 = __floats2half2_rn(x1.z*rn, x1.w*rn);
    __half2 h4 = __floats2half2_rn(x2.x*rn, x2.y*rn);
    __half2 h5 = __floats2half2_rn(x2.z*rn, x2.w*rn);
    uint2* zh = (uint2*)(g_zh + idx * FAC);
    zh[0] = make_uint2(*(unsigned*)&h0, *(unsigned*)&h1);
    zh[1] = make_uint2(*(unsigned*)&h2, *(unsigned*)&h3);
    zh[2] = make_uint2(*(unsigned*)&h4, *(unsigned*)&h5);
}

// ---------------------------------------------------------------------------
__device__ __forceinline__ void cvt12(uint2 a0, uint2 a1, uint2 a2, float* f) {
    float2 t;
    t = __half22float2(*(__half2*)&a0.x); f[0] = t.x;  f[1] = t.y;
    t = __half22float2(*(__half2*)&a0.y); f[2] = t.x;  f[3] = t.y;
    t = __half22float2(*(__half2*)&a1.x); f[4] = t.x;  f[5] = t.y;
    t = __half22float2(*(__half2*)&a1.y); f[6] = t.x;  f[7] = t.y;
    t = __half22float2(*(__half2*)&a2.x); f[8] = t.x;  f[9] = t.y;
    t = __half22float2(*(__half2*)&a2.y); f[10] = t.x; f[11] = t.y;
}

// Fused routing layer: gather neighbor z to smem once, run all 6 iterations
// with c in registers. 8 lanes per node (lane = capsule), 4 nodes/warp,
// 16 nodes per 128-thread block.
__global__ void __launch_bounds__(128) routing_layer(int n) {
    extern __shared__ char sm[];
    int lane = threadIdx.x & 31;
    int warp = threadIdx.x >> 5;
    int group = lane >> 3;
    int cap = lane & 7;
    unsigned mask = 0xFFu << (group << 3);
    int local = warp * 4 + group;
    int slot = blockIdx.x * 16 + local;
    bool valid = slot < n;
    int node = valid ? g_perm[slot] : 0;

    int s = 0, deg = 0;
    if (valid) { s = g_rowptr[node]; deg = g_rowptr[node + 1] - s; }
    int cached = min(deg, CAP);

    char* slab = sm + local * NSTRIDE;

    // ---- fill: gather cached neighbor z rows (fp16, 192B each) ----
    for (int e = 0; e < cached; e++) {
        int src = g_colsrc[s + e];
        const uint4* gp = (const uint4*)(g_zh + (size_t)src * D);
        uint4* row = (uint4*)(slab + e * 192);
        row[cap] = gp[cap];
        if (cap < 4) row[8 + cap] = gp[8 + cap];
    }

    // ---- z_self (fp32) from g_c; c init = z ----
    float z[12], c[12];
    if (valid) {
        const float4* cb = (const float4*)(g_c + node * D + cap * FAC);
        float4 a0 = cb[0], a1 = cb[1], a2 = cb[2];
        float t[12] = {a0.x, a0.y, a0.z, a0.w, a1.x, a1.y, a1.z, a1.w,
                       a2.x, a2.y, a2.z, a2.w};
        float ss = 0.f;
#pragma unroll
        for (int i = 0; i < 12; i++) { t[i] = fmaxf(t[i], 0.f); ss += t[i] * t[i]; }
        float rn = rsqrtf(ss + 1e-12f);
#pragma unroll
        for (int i = 0; i < 12; i++) { z[i] = t[i] * rn; c[i] = z[i]; }
    }
    __syncwarp();

    // ---- 6 routing iterations, all from smem / registers ----
    for (int it = 0; it < 6; it++) {
        float acc[12];
#pragma unroll
        for (int i = 0; i < 12; i++) acc[i] = 0.f;

        int e = 0;
        // 2-edge unrolled: two independent shuffle/exp chains in flight
        for (; e + 1 < cached; e += 2) {
            const uint2* rA = (const uint2*)(slab + e * 192 + cap * 24);
            const uint2* rB = (const uint2*)(slab + (e + 1) * 192 + cap * 24);
            uint2 A0 = rA[0], A1 = rA[1], A2 = rA[2];
            uint2 B0 = rB[0], B1 = rB[1], B2 = rB[2];
            float fA[12], fB[12];
            cvt12(A0, A1, A2, fA);
            cvt12(B0, B1, B2, fB);
            float attA = 0.f, attB = 0.f;
#pragma unroll
            for (int i = 0; i < 12; i++) { attA += fA[i] * c[i]; attB += fB[i] * c[i]; }
            // z,c unit vectors -> att in [-1,1]: exp safe without max-sub
            float exA = __expf(attA), exB = __expf(attB);
            float sA = exA, sB = exB;
            sA += __shfl_xor_sync(mask, sA, 1); sB += __shfl_xor_sync(mask, sB, 1);
            sA += __shfl_xor_sync(mask, sA, 2); sB += __shfl_xor_sync(mask, sB, 2);
            sA += __shfl_xor_sync(mask, sA, 4); sB += __shfl_xor_sync(mask, sB, 4);
            float pA = __fdividef(exA, sA);
            float pB = __fdividef(exB, sB);
#pragma unroll
            for (int i = 0; i < 12; i++) acc[i] += pA * fA[i];
#pragma unroll
            for (int i = 0; i < 12; i++) acc[i] += pB * fB[i];
        }
        if (e < cached) {
            const uint2* rA = (const uint2*)(slab + e * 192 + cap * 24);
            uint2 A0 = rA[0], A1 = rA[1], A2 = rA[2];
            float fA[12];
            cvt12(A0, A1, A2, fA);
            float att = 0.f;
#pragma unroll
            for (int i = 0; i < 12; i++) att += fA[i] * c[i];
            float ex = __expf(att);
            float sm_ = ex;
            sm_ += __shfl_xor_sync(mask, sm_, 1);
            sm_ += __shfl_xor_sync(mask, sm_, 2);
            sm_ += __shfl_xor_sync(mask, sm_, 4);
            float p = __fdividef(ex, sm_);
#pragma unroll
            for (int i = 0; i < 12; i++) acc[i] += p * fA[i];
        }
        // rare overflow edges streamed from gmem, preserving order
        for (int e2 = cached; e2 < deg; e2++) {
            const uint2* gz = (const uint2*)(g_zh + (size_t)g_colsrc[s + e2] * D + cap * 24 / 2);
            uint2 A0 = gz[0], A1 = gz[1], A2 = gz[2];
            float fA[12];
            cvt12(A0, A1, A2, fA);
            float att = 0.f;
#pragma unroll
            for (int i = 0; i < 12; i++) att += fA[i] * c[i];
            float ex = __expf(att);
            float sm_ = ex;
            sm_ += __shfl_xor_sync(mask, sm_, 1);
            sm_ += __shfl_xor_sync(mask, sm_, 2);
            sm_ += __shfl_xor_sync(mask, sm_, 4);
            float p = __fdividef(ex, sm_);
#pragma unroll
            for (int i = 0; i < 12; i++) acc[i] += p * fA[i];
        }

        float v[12];
        float ss = 0.f;
#pragma unroll
        for (int i = 0; i < 12; i++) { v[i] = z[i] + acc[i]; ss += v[i] * v[i]; }
        float rn = rsqrtf(ss + 1e-12f);
#pragma unroll
        for (int i = 0; i < 12; i++) c[i] = v[i] * rn;
    }

    if (valid) {
        float4* co = (float4*)(g_c + node * D + cap * FAC);
        co[0] = make_float4(c[0], c[1], c[2], c[3]);
        co[1] = make_float4(c[4], c[5], c[6], c[7]);
        co[2] = make_float4(c[8], c[9], c[10], c[11]);
    }
}

// ---------------------------------------------------------------------------
__global__ void relu_out(float* __restrict__ out, int tot) {
    int i = blockIdx.x * blockDim.x + threadIdx.x;
    if (i < tot) out[i] = fmaxf(g_c[i], 0.f);
}

// ---------------------------------------------------------------------------
extern "C" void kernel_launch(void* const* d_in, const int* in_sizes, int n_in,
                              void* d_out, int out_size) {
    const float* X     = (const float*)d_in[0];
    const int*   edges = (const int*)d_in[1];
    const float* W     = (const float*)d_in[2];
    const float* b     = (const float*)d_in[3];
    int n = in_sizes[0] / 256;   // 50000
    int m = in_sizes[1] / 2;     // 800000

    cudaFuncSetAttribute(routing_layer,
                         cudaFuncAttributeMaxDynamicSharedMemorySize, ROUTE_SMEM);

    // weights transpose + init layer
    wt_kernel<<<(D * 256 + 255) / 256, 256>>>(W);
    init_gemm<<<(n + 31) / 32, 96>>>(X, b, n);

    // CSR by dst (deterministic: rows sorted by src)
    zero_kernel<<<(n + 255) / 256, 256>>>(n);
    hist_kernel<<<(m + 255) / 256, 256>>>(edges, m);
    scan_kernel<<<1, 1024>>>(n);
    scatter_kernel<<<(m + 255) / 256, 256>>>(edges, m);
    sort_rows<<<(n + 255) / 256, 256>>>(n);

    // degree-balanced node permutation
    dhist_kernel<<<(n + 255) / 256, 256>>>(n);
    dscan_kernel<<<1, 32>>>();
    dscatter_kernel<<<(n + 255) / 256, 256>>>(n);

    // 4 layers: prep (zh) + fused 6-iteration routing
    for (int layer = 0; layer < 4; layer++) {
        prep_kernel<<<(n * KCAP + 255) / 256, 256>>>(n);
        routing_layer<<<(n + 15) / 16, 128, ROUTE_SMEM>>>(n);
    }

    relu_out<<<(n * D + 255) / 256, 256>>>((float*)d_out, n * D);
}